// round 4
// baseline (speedup 1.0000x reference)
#include <cuda_runtime.h>
#include <cstdint>

// BiologicalWorkingMemory: B x (S=8 slots, D=64 dims) fused update.
// 8 lanes per batch, 4 batches per warp, 128 threads/block -> 16 batches/block.
//
// R3: m lives in SMEM during the 56-pair sequential chain. The chain maintains
// the Gram matrix G (replicated) + the composed linear operator L (one column
// per lane, 1 FMA/pair). Decay (x0.95) is folded into L's init; refresh /
// deactivation / write-blend scales are folded into L's rows. m_out = L*m0 is
// applied as a dense 8x8 pass from SMEM. Peak live registers ~100 -> 5 CTAs/SM.

static __device__ __forceinline__ float gsum8(float v) {
    v += __shfl_xor_sync(0xffffffffu, v, 1);
    v += __shfl_xor_sync(0xffffffffu, v, 2);
    v += __shfl_xor_sync(0xffffffffu, v, 4);
    return v;
}

static __device__ __forceinline__ float dot4(float4 a, float4 b) {
    return (a.x * b.x + a.y * b.y) + (a.z * b.z + a.w * b.w);
}

// symmetric index for a<=b into 36-entry triangle
#define GIDX(a, b) ((a) * 8 - (a) * ((a) + 1) / 2 + (b))
#define GSYM(a, b) ((a) <= (b) ? GIDX(a, b) : GIDX(b, a))

__global__ __launch_bounds__(128, 5) void wm_kernel(
    const float* __restrict__ mem,        // (B,8,64)
    const float* __restrict__ act_in,     // (B,8)
    const float* __restrict__ gate_in,    // (B,8)
    const float* __restrict__ thr_in,     // (B,8)
    const float* __restrict__ refresh_in, // (B,8)
    const float* __restrict__ intf,       // (B,8,8)
    const float* __restrict__ maint_in,   // (B,8)
    const float* __restrict__ x_in,       // (B,64)
    const float* __restrict__ gsig_in,    // (B,8)
    const float* __restrict__ rsig_in,    // (B,8)
    const void* __restrict__ dt_ptr,
    float* __restrict__ out,
    int B)
{
    // 16 batches * (8 slots * 17 float4 + pad) ; slot stride 17 f4 avoids bank conflicts
    __shared__ float4 sm[16 * 137];

    const unsigned FULL = 0xffffffffu;
    const int lane = threadIdx.x & 31;
    const int warp = blockIdx.x * (blockDim.x >> 5) + (threadIdx.x >> 5);
    const int grp  = lane >> 3;   // batch within warp
    const int r    = lane & 7;    // slot rank / chunk rank / L column
    const int b    = warp * 4 + grp;
    const bool valid = (b < B);
    const int bb = valid ? b : (B - 1);
    const int wb = ((threadIdx.x >> 5) << 2) | grp;   // batch within block
    const int base4 = wb * 137;

    // dt may arrive as int32 or float32 scalar; decode by bit-pattern heuristic.
    float dtf;
    {
        int di = *(const int*)dt_ptr;
        dtf = (di > -16777216 && di < 16777216) ? (float)di : __int_as_float(di);
    }

    // ---- early per-slot scalar: activity (needed pre-chain) ----
    const size_t sb = (size_t)bb * 8 + r;
    const float act0 = act_in[sb];

    // interference row r (8 floats)
    const float4* ip = (const float4*)(intf + (size_t)bb * 64 + (size_t)r * 8);
    const float4 I0 = ip[0], I1 = ip[1];
    const float Irow[8] = {I0.x, I0.y, I0.z, I0.w, I1.x, I1.y, I1.z, I1.w};

    // ---- pass A: first halves (lane r owns words [r*4, r*4+4) of each slot) ----
    const float4* mp4 = (const float4*)(mem + (size_t)bb * 512);
    float4 m4[8];
    float G[36];
#pragma unroll
    for (int s = 0; s < 8; s++) m4[s] = mp4[s * 16 + r];
#pragma unroll
    for (int s = 0; s < 8; s++) sm[base4 + s * 17 + r] = m4[s];
#pragma unroll
    for (int a = 0; a < 8; a++)
#pragma unroll
        for (int c = a; c < 8; c++)
            G[GIDX(a, c)] = dot4(m4[a], m4[c]);

    // ---- pass B: second halves (words [32 + r*4, 32 + r*4 + 4)) ----
#pragma unroll
    for (int s = 0; s < 8; s++) m4[s] = mp4[s * 16 + 8 + r];
#pragma unroll
    for (int s = 0; s < 8; s++) sm[base4 + s * 17 + 8 + r] = m4[s];
#pragma unroll
    for (int a = 0; a < 8; a++)
#pragma unroll
        for (int c = a; c < 8; c++)
            G[GIDX(a, c)] += dot4(m4[a], m4[c]);

    // reduce all 36 Gram entries across the 8 lanes (pipelined)
#pragma unroll
    for (int t = 0; t < 36; t++) G[t] = gsum8(G[t]);

    // ---- prefetch epilogue operands (latency hidden under the chain) ----
    const float gate = gate_in[sb];
    const float thr  = thr_in[sb];
    const float rstr = refresh_in[sb];
    const float maint= maint_in[sb];
    const float gsig = gsig_in[sb];
    const float rsig = rsig_in[sb];
    const float4* xp4 = (const float4*)(x_in + (size_t)bb * 64);
    const float4 xA = xp4[r];
    const float4 xB = xp4[8 + r];

    // ---- activity decay + masks ----
    const float adec = act0 * 0.9f;
    const unsigned actBall = __ballot_sync(FULL, adec > 0.1f);
    const unsigned actMask = (actBall >> (grp * 8)) & 0xffu;
    const unsigned avBall = __ballot_sync(FULL, act0 < 0.2f);
    const unsigned avMask = (avBall >> (grp * 8)) & 0xffu;

    // ---- target slot: argmin with jnp tie-break (lowest index) ----
    const float INF = __int_as_float(0x7f800000);
    float key = avMask ? ((act0 < 0.2f) ? act0 : INF) : act0;
    int idx = r;
#pragma unroll
    for (int off = 1; off < 8; off <<= 1) {
        float ov = __shfl_xor_sync(FULL, key, off);
        int   oi = __shfl_xor_sync(FULL, idx, off);
        if (ov < key || (ov == key && oi < idx)) { key = ov; idx = oi; }
    }
    const int ts = idx;  // uniform within group

    // ---- sequential interference chain on G; L tracks the composed operator.
    //      Gram is on UN-decayed m (sim is scale-invariant); decay folded into L.
    float Lcol[8];
#pragma unroll
    for (int i = 0; i < 8; i++) Lcol[i] = (i == r) ? 0.95f : 0.0f;

#pragma unroll
    for (int i = 0; i < 8; i++) {
        float Kc[8];
#pragma unroll
        for (int j = 0; j < 8; j++) {
            if (j == i) { Kc[j] = 0.0f; continue; }
            const float Iv = __shfl_sync(FULL, Irow[j], i, 8);
            const bool cond = ((actMask >> i) & 1u) && ((actMask >> j) & 1u);
            Kc[j] = cond ? 0.1f * Iv : 0.0f;
        }
#pragma unroll
        for (int j = 0; j < 8; j++) {
            if (i == j) continue;
            const float Gij = G[GSYM(i, j)];
            const float Gjj = G[GIDX(j, j)];
            const float c = Kc[j] * Gij * rsqrtf(G[GIDX(i, i)] * Gjj);
            const float GiiNew = fmaf(c, fmaf(c, Gjj, -2.0f * Gij), G[GIDX(i, i)]);
#pragma unroll
            for (int k = 0; k < 8; k++) {
                if (k == i) continue;
                G[GSYM(i, k)] = fmaf(-c, G[GSYM(j, k)], G[GSYM(i, k)]);
            }
            G[GIDX(i, i)] = GiiNew;
            Lcol[i] = fmaf(-c, Lcol[j], Lcol[i]);   // operator row-op, 1 FMA/lane
        }
    }

    // ---- gating / write ----
    const float gv = 0.7f * gate + 0.3f * __saturatef(gsig);
    const float gs = __shfl_sync(FULL, gv, ts, 8);
    const float th = __shfl_sync(FULL, thr, ts, 8);
    const bool write = gs > th;

    const float in2 = gsum8(dot4(xA, xA) + dot4(xB, xB));
    const float inorm = sqrtf(in2);

    float a = adec;
    if (write && r == ts) a = inorm;

    // ---- refresh ----
    const float ru = __saturatef(rsig);
    const float rs = (ru > 0.1f) ? rstr * ru : 0.0f;
    a += rs;

    // ---- maintenance ----
    const float mc = (a > 0.1f)
        ? fmaf(fmaf(0.5f, a, -maint), 0.1f * dtf, maint)
        : maint * 0.95f;

    // ---- capacity limiting: rank active slots ascending (stable ties) ----
    float ab[8];
#pragma unroll
    for (int s = 0; s < 8; s++) ab[s] = __shfl_sync(FULL, a, s, 8);
    const unsigned activeBall = __ballot_sync(FULL, a > 0.1f);
    const unsigned activeMask = (activeBall >> (grp * 8)) & 0xffu;
    const int ndeact = __popc(activeMask) - 4;
    int rank = 0;
#pragma unroll
    for (int s = 0; s < 8; s++) {
        const bool sa = (activeMask >> s) & 1u;
        if (sa && (ab[s] < a || (ab[s] == a && s < r))) rank++;
    }
    const bool active_r = (activeMask >> r) & 1u;
    const bool deact = active_r && (rank < ndeact);
    const float afin = deact ? a * 0.5f : a;
    const unsigned deBall = __ballot_sync(FULL, deact);
    const unsigned deMask = (deBall >> (grp * 8)) & 0xffu;

    // per-slot refresh scales broadcast
    float rsb[8];
#pragma unroll
    for (int s = 0; s < 8; s++) rsb[s] = __shfl_sync(FULL, rs, s, 8);

    // ---- fold all row scales into L ----
    const float wgt = write ? gs * 0.3f : 0.0f;
#pragma unroll
    for (int i = 0; i < 8; i++) {
        float rowS = (1.0f + rsb[i]) * (((deMask >> i) & 1u) ? 0.7f : 1.0f);
        if (i == ts) rowS *= (1.0f - wgt);
        Lcol[i] *= rowS;
    }
    // input-blend coefficient for the target row (post-scale)
    const float wS = wgt * (1.0f + rsb[ts]) * (((deMask >> ts) & 1u) ? 0.7f : 1.0f);

    // ---- dense apply m_out = L * m0 from SMEM, fused store ----
    float4* op4 = (float4*)(out + (size_t)b * 512);
#pragma unroll
    for (int p = 0; p < 2; p++) {
        float4 accA[4], accB[4];
#pragma unroll
        for (int q = 0; q < 4; q++) {
            accA[q] = make_float4(0.f, 0.f, 0.f, 0.f);
            accB[q] = make_float4(0.f, 0.f, 0.f, 0.f);
        }
#pragma unroll
        for (int k = 0; k < 8; k++) {
            const float4 ck0 = sm[base4 + k * 17 + r];
            const float4 ck1 = sm[base4 + k * 17 + 8 + r];
#pragma unroll
            for (int q = 0; q < 4; q++) {
                const float Lik = __shfl_sync(FULL, Lcol[p * 4 + q], k, 8);
                accA[q].x = fmaf(Lik, ck0.x, accA[q].x);
                accA[q].y = fmaf(Lik, ck0.y, accA[q].y);
                accA[q].z = fmaf(Lik, ck0.z, accA[q].z);
                accA[q].w = fmaf(Lik, ck0.w, accA[q].w);
                accB[q].x = fmaf(Lik, ck1.x, accB[q].x);
                accB[q].y = fmaf(Lik, ck1.y, accB[q].y);
                accB[q].z = fmaf(Lik, ck1.z, accB[q].z);
                accB[q].w = fmaf(Lik, ck1.w, accB[q].w);
            }
        }
        if (valid) {
#pragma unroll
            for (int q = 0; q < 4; q++) {
                const int i = p * 4 + q;
                float4 oA = accA[q], oB = accB[q];
                if (i == ts) {
                    oA.x = fmaf(wS, xA.x, oA.x);
                    oA.y = fmaf(wS, xA.y, oA.y);
                    oA.z = fmaf(wS, xA.z, oA.z);
                    oA.w = fmaf(wS, xA.w, oA.w);
                    oB.x = fmaf(wS, xB.x, oB.x);
                    oB.y = fmaf(wS, xB.y, oB.y);
                    oB.z = fmaf(wS, xB.z, oB.z);
                    oB.w = fmaf(wS, xB.w, oB.w);
                }
                op4[i * 16 + r]     = oA;
                op4[i * 16 + 8 + r] = oB;
            }
        }
    }

    // ---- per-batch reductions + scalar outputs ----
    const float tot  = gsum8(afin);
    const float msum = gsum8(mc);
    const unsigned loadBall = __ballot_sync(FULL, afin > 0.1f);
    const int mload = __popc((loadBall >> (grp * 8)) & 0xffu);

    const size_t OA  = (size_t)B * 512;      // m size
    const size_t SB8 = (size_t)B * 8;
    if (valid) {
        out[OA + (size_t)b * 8 + r]           = afin;  // a
        out[OA + SB8 + (size_t)b * 8 + r]     = gv;    // g
        out[OA + 2 * SB8 + (size_t)b * 8 + r] = mc;    // mc
        if (r == 0) {
            out[OA + 3 * SB8 + (size_t)b]                 = (float)mload;
            out[OA + 3 * SB8 + (size_t)B + (size_t)b]     = tot;
            out[OA + 3 * SB8 + 2 * (size_t)B + (size_t)b] = msum * 0.125f;
        }
    }
}

extern "C" void kernel_launch(void* const* d_in, const int* in_sizes, int n_in,
                              void* d_out, int out_size)
{
    const int B = in_sizes[0] / 512;   // B*S*D / (8*64)
    const int threads = 128;           // 4 warps * 4 batches = 16 batches/block
    const int batchesPerBlock = 16;
    const int grid = (B + batchesPerBlock - 1) / batchesPerBlock;
    wm_kernel<<<grid, threads>>>(
        (const float*)d_in[0], (const float*)d_in[1], (const float*)d_in[2],
        (const float*)d_in[3], (const float*)d_in[4], (const float*)d_in[5],
        (const float*)d_in[6], (const float*)d_in[7], (const float*)d_in[8],
        (const float*)d_in[9], (const void*)d_in[10],
        (float*)d_out, B);
}

// round 7
// speedup vs baseline: 1.3872x; 1.3872x over previous
#include <cuda_runtime.h>
#include <cstdint>

// BiologicalWorkingMemory: B x (S=8 slots, D=64 dims) fused update.
// 8 lanes per batch, 4 batches per warp, 128 threads/block -> 16 batches/block.
//
// Design: m lives in SMEM during the 56-pair sequential chain. The chain
// maintains the Gram matrix G (replicated per lane) + the composed linear
// operator L (one column per lane, 1 FMA/pair). Decay (x0.95) folded into L's
// init (sim is scale-invariant, so G stays un-decayed); refresh/deactivation/
// write-blend scales folded into L's rows. m_out = L*m0 applied as a dense
// 8x8 pass from SMEM (each thread reads only its own SMEM writes -> no
// barriers). launch_bounds(128,4): <=128 regs (natural allocation), 4 CTAs/SM.

static __device__ __forceinline__ float gsum8(float v) {
    v += __shfl_xor_sync(0xffffffffu, v, 1);
    v += __shfl_xor_sync(0xffffffffu, v, 2);
    v += __shfl_xor_sync(0xffffffffu, v, 4);
    return v;
}

static __device__ __forceinline__ float dot4(float4 a, float4 b) {
    return (a.x * b.x + a.y * b.y) + (a.z * b.z + a.w * b.w);
}

// symmetric index for a<=b into 36-entry triangle
#define GIDX(a, b) ((a) * 8 - (a) * ((a) + 1) / 2 + (b))
#define GSYM(a, b) ((a) <= (b) ? GIDX(a, b) : GIDX(b, a))

__global__ __launch_bounds__(128, 4) void wm_kernel(
    const float* __restrict__ mem,        // (B,8,64)
    const float* __restrict__ act_in,     // (B,8)
    const float* __restrict__ gate_in,    // (B,8)
    const float* __restrict__ thr_in,     // (B,8)
    const float* __restrict__ refresh_in, // (B,8)
    const float* __restrict__ intf,       // (B,8,8)
    const float* __restrict__ maint_in,   // (B,8)
    const float* __restrict__ x_in,       // (B,64)
    const float* __restrict__ gsig_in,    // (B,8)
    const float* __restrict__ rsig_in,    // (B,8)
    const void* __restrict__ dt_ptr,
    float* __restrict__ out,
    int B)
{
    // 16 batches * (8 slots * 17 float4 + pad); slot stride 17 f4 avoids bank conflicts
    __shared__ float4 sm[16 * 137];

    const unsigned FULL = 0xffffffffu;
    const int lane = threadIdx.x & 31;
    const int warp = blockIdx.x * (blockDim.x >> 5) + (threadIdx.x >> 5);
    const int grp  = lane >> 3;   // batch within warp
    const int r    = lane & 7;    // slot rank / chunk rank / L column
    const int b    = warp * 4 + grp;
    const bool valid = (b < B);
    const int bb = valid ? b : (B - 1);
    const int wb = ((threadIdx.x >> 5) << 2) | grp;   // batch within block
    const int base4 = wb * 137;

    // dt may arrive as int32 or float32 scalar; decode by bit-pattern heuristic.
    float dtf;
    {
        int di = *(const int*)dt_ptr;
        dtf = (di > -16777216 && di < 16777216) ? (float)di : __int_as_float(di);
    }

    // ---- early per-slot scalar: activity (needed pre-chain) ----
    const size_t sb = (size_t)bb * 8 + r;
    const float act0 = act_in[sb];

    // interference row r (8 floats)
    const float4* ip = (const float4*)(intf + (size_t)bb * 64 + (size_t)r * 8);
    const float4 I0 = ip[0], I1 = ip[1];
    const float Irow[8] = {I0.x, I0.y, I0.z, I0.w, I1.x, I1.y, I1.z, I1.w};

    // ---- pass A: first halves (lane r owns words [r*4, r*4+4) of each slot) ----
    const float4* mp4 = (const float4*)(mem + (size_t)bb * 512);
    float4 m4[8];
    float G[36];
#pragma unroll
    for (int s = 0; s < 8; s++) m4[s] = mp4[s * 16 + r];
#pragma unroll
    for (int s = 0; s < 8; s++) sm[base4 + s * 17 + r] = m4[s];
#pragma unroll
    for (int a = 0; a < 8; a++)
#pragma unroll
        for (int c = a; c < 8; c++)
            G[GIDX(a, c)] = dot4(m4[a], m4[c]);

    // ---- pass B: second halves (words [32 + r*4, 32 + r*4 + 4)) ----
#pragma unroll
    for (int s = 0; s < 8; s++) m4[s] = mp4[s * 16 + 8 + r];
#pragma unroll
    for (int s = 0; s < 8; s++) sm[base4 + s * 17 + 8 + r] = m4[s];
#pragma unroll
    for (int a = 0; a < 8; a++)
#pragma unroll
        for (int c = a; c < 8; c++)
            G[GIDX(a, c)] += dot4(m4[a], m4[c]);

    // reduce all 36 Gram entries across the 8 lanes (pipelined)
#pragma unroll
    for (int t = 0; t < 36; t++) G[t] = gsum8(G[t]);

    // ---- prefetch epilogue operands (latency hidden under the chain) ----
    const float gate = gate_in[sb];
    const float thr  = thr_in[sb];
    const float rstr = refresh_in[sb];
    const float maint= maint_in[sb];
    const float gsig = gsig_in[sb];
    const float rsig = rsig_in[sb];
    const float4* xp4 = (const float4*)(x_in + (size_t)bb * 64);
    const float4 xA = xp4[r];
    const float4 xB = xp4[8 + r];

    // ---- activity decay + masks ----
    const float adec = act0 * 0.9f;
    const unsigned actBall = __ballot_sync(FULL, adec > 0.1f);
    const unsigned actMask = (actBall >> (grp * 8)) & 0xffu;
    const unsigned avBall = __ballot_sync(FULL, act0 < 0.2f);
    const unsigned avMask = (avBall >> (grp * 8)) & 0xffu;

    // ---- target slot: argmin with jnp tie-break (lowest index) ----
    const float INF = __int_as_float(0x7f800000);
    float key = avMask ? ((act0 < 0.2f) ? act0 : INF) : act0;
    int idx = r;
#pragma unroll
    for (int off = 1; off < 8; off <<= 1) {
        float ov = __shfl_xor_sync(FULL, key, off);
        int   oi = __shfl_xor_sync(FULL, idx, off);
        if (ov < key || (ov == key && oi < idx)) { key = ov; idx = oi; }
    }
    const int ts = idx;  // uniform within group

    // ---- sequential interference chain on G; L tracks the composed operator.
    //      Gram is on UN-decayed m (sim is scale-invariant); decay folded into L.
    float Lcol[8];
#pragma unroll
    for (int i = 0; i < 8; i++) Lcol[i] = (i == r) ? 0.95f : 0.0f;

#pragma unroll
    for (int i = 0; i < 8; i++) {
        float Kc[8];
#pragma unroll
        for (int j = 0; j < 8; j++) {
            if (j == i) { Kc[j] = 0.0f; continue; }
            const float Iv = __shfl_sync(FULL, Irow[j], i, 8);
            const bool cond = ((actMask >> i) & 1u) && ((actMask >> j) & 1u);
            Kc[j] = cond ? 0.1f * Iv : 0.0f;
        }
#pragma unroll
        for (int j = 0; j < 8; j++) {
            if (i == j) continue;
            const float Gij = G[GSYM(i, j)];
            const float Gjj = G[GIDX(j, j)];
            const float c = Kc[j] * Gij * rsqrtf(G[GIDX(i, i)] * Gjj);
            const float GiiNew = fmaf(c, fmaf(c, Gjj, -2.0f * Gij), G[GIDX(i, i)]);
#pragma unroll
            for (int k = 0; k < 8; k++) {
                if (k == i) continue;
                G[GSYM(i, k)] = fmaf(-c, G[GSYM(j, k)], G[GSYM(i, k)]);
            }
            G[GIDX(i, i)] = GiiNew;
            Lcol[i] = fmaf(-c, Lcol[j], Lcol[i]);   // operator row-op, 1 FMA/lane
        }
    }

    // ---- gating / write ----
    const float gv = 0.7f * gate + 0.3f * __saturatef(gsig);
    const float gs = __shfl_sync(FULL, gv, ts, 8);
    const float th = __shfl_sync(FULL, thr, ts, 8);
    const bool write = gs > th;

    const float in2 = gsum8(dot4(xA, xA) + dot4(xB, xB));
    const float inorm = sqrtf(in2);

    float a = adec;
    if (write && r == ts) a = inorm;

    // ---- refresh ----
    const float ru = __saturatef(rsig);
    const float rs = (ru > 0.1f) ? rstr * ru : 0.0f;
    a += rs;

    // ---- maintenance ----
    const float mc = (a > 0.1f)
        ? fmaf(fmaf(0.5f, a, -maint), 0.1f * dtf, maint)
        : maint * 0.95f;

    // ---- capacity limiting: rank active slots ascending (stable ties) ----
    float ab[8];
#pragma unroll
    for (int s = 0; s < 8; s++) ab[s] = __shfl_sync(FULL, a, s, 8);
    const unsigned activeBall = __ballot_sync(FULL, a > 0.1f);
    const unsigned activeMask = (activeBall >> (grp * 8)) & 0xffu;
    const int ndeact = __popc(activeMask) - 4;
    int rank = 0;
#pragma unroll
    for (int s = 0; s < 8; s++) {
        const bool sa = (activeMask >> s) & 1u;
        if (sa && (ab[s] < a || (ab[s] == a && s < r))) rank++;
    }
    const bool active_r = (activeMask >> r) & 1u;
    const bool deact = active_r && (rank < ndeact);
    const float afin = deact ? a * 0.5f : a;
    const unsigned deBall = __ballot_sync(FULL, deact);
    const unsigned deMask = (deBall >> (grp * 8)) & 0xffu;

    // per-slot refresh scales broadcast
    float rsb[8];
#pragma unroll
    for (int s = 0; s < 8; s++) rsb[s] = __shfl_sync(FULL, rs, s, 8);

    // ---- fold all row scales into L ----
    const float wgt = write ? gs * 0.3f : 0.0f;
#pragma unroll
    for (int i = 0; i < 8; i++) {
        float rowS = (1.0f + rsb[i]) * (((deMask >> i) & 1u) ? 0.7f : 1.0f);
        if (i == ts) rowS *= (1.0f - wgt);
        Lcol[i] *= rowS;
    }
    // input-blend coefficient for the target row (post-scale)
    const float wS = wgt * (1.0f + rsb[ts]) * (((deMask >> ts) & 1u) ? 0.7f : 1.0f);

    // ---- dense apply m_out = L * m0 from SMEM, fused store ----
    float4* op4 = (float4*)(out + (size_t)b * 512);
#pragma unroll
    for (int p = 0; p < 2; p++) {
        float4 accA[4], accB[4];
#pragma unroll
        for (int q = 0; q < 4; q++) {
            accA[q] = make_float4(0.f, 0.f, 0.f, 0.f);
            accB[q] = make_float4(0.f, 0.f, 0.f, 0.f);
        }
#pragma unroll
        for (int k = 0; k < 8; k++) {
            const float4 ck0 = sm[base4 + k * 17 + r];
            const float4 ck1 = sm[base4 + k * 17 + 8 + r];
#pragma unroll
            for (int q = 0; q < 4; q++) {
                const float Lik = __shfl_sync(FULL, Lcol[p * 4 + q], k, 8);
                accA[q].x = fmaf(Lik, ck0.x, accA[q].x);
                accA[q].y = fmaf(Lik, ck0.y, accA[q].y);
                accA[q].z = fmaf(Lik, ck0.z, accA[q].z);
                accA[q].w = fmaf(Lik, ck0.w, accA[q].w);
                accB[q].x = fmaf(Lik, ck1.x, accB[q].x);
                accB[q].y = fmaf(Lik, ck1.y, accB[q].y);
                accB[q].z = fmaf(Lik, ck1.z, accB[q].z);
                accB[q].w = fmaf(Lik, ck1.w, accB[q].w);
            }
        }
        if (valid) {
#pragma unroll
            for (int q = 0; q < 4; q++) {
                const int i = p * 4 + q;
                float4 oA = accA[q], oB = accB[q];
                if (i == ts) {
                    oA.x = fmaf(wS, xA.x, oA.x);
                    oA.y = fmaf(wS, xA.y, oA.y);
                    oA.z = fmaf(wS, xA.z, oA.z);
                    oA.w = fmaf(wS, xA.w, oA.w);
                    oB.x = fmaf(wS, xB.x, oB.x);
                    oB.y = fmaf(wS, xB.y, oB.y);
                    oB.z = fmaf(wS, xB.z, oB.z);
                    oB.w = fmaf(wS, xB.w, oB.w);
                }
                op4[i * 16 + r]     = oA;
                op4[i * 16 + 8 + r] = oB;
            }
        }
    }

    // ---- per-batch reductions + scalar outputs ----
    const float tot  = gsum8(afin);
    const float msum = gsum8(mc);
    const unsigned loadBall = __ballot_sync(FULL, afin > 0.1f);
    const int mload = __popc((loadBall >> (grp * 8)) & 0xffu);

    const size_t OA  = (size_t)B * 512;      // m size
    const size_t SB8 = (size_t)B * 8;
    if (valid) {
        out[OA + (size_t)b * 8 + r]           = afin;  // a
        out[OA + SB8 + (size_t)b * 8 + r]     = gv;    // g
        out[OA + 2 * SB8 + (size_t)b * 8 + r] = mc;    // mc
        if (r == 0) {
            out[OA + 3 * SB8 + (size_t)b]                 = (float)mload;
            out[OA + 3 * SB8 + (size_t)B + (size_t)b]     = tot;
            out[OA + 3 * SB8 + 2 * (size_t)B + (size_t)b] = msum * 0.125f;
        }
    }
}

extern "C" void kernel_launch(void* const* d_in, const int* in_sizes, int n_in,
                              void* d_out, int out_size)
{
    const int B = in_sizes[0] / 512;   // B*S*D / (8*64)
    const int threads = 128;           // 4 warps * 4 batches = 16 batches/block
    const int batchesPerBlock = 16;
    const int grid = (B + batchesPerBlock - 1) / batchesPerBlock;
    wm_kernel<<<grid, threads>>>(
        (const float*)d_in[0], (const float*)d_in[1], (const float*)d_in[2],
        (const float*)d_in[3], (const float*)d_in[4], (const float*)d_in[5],
        (const float*)d_in[6], (const float*)d_in[7], (const float*)d_in[8],
        (const float*)d_in[9], (const void*)d_in[10],
        (float*)d_out, B);
}